// round 1
// baseline (speedup 1.0000x reference)
#include <cuda_runtime.h>
#include <math.h>

// Problem constants
// B=4, T=1024, C=2048, NH=16, HS=128, NLQ=512, NLKV=512, DHR=64
// scale = 1/sqrt(HS + DHR) = 1/sqrt(192)

// ---------------- scratch (device globals; no allocation allowed) -------------
__device__ float g_keff[16L * 512 * 512];       //  16 MB  k_eff[h][q][k]
__device__ float g_M[512L * 2048];              //   4 MB  M[k][c] = (W_uv^T @ W_o^T)
__device__ float g_cq[4096L * 512];             //   8 MB  c_q
__device__ float g_ckv[4096L * 512];            //   8 MB  c_kv
__device__ float g_ckr[4096L * 64];             //   1 MB  c_kr (pre-rope)
__device__ float g_cqr[4096L * 1024];           //  16 MB  c_qr (pre-rope)
__device__ float g_qr[4096L * 1024];            //  16 MB  q_r (roped)
__device__ float g_kr[4096L * 64];              //   1 MB  k_r (roped)
__device__ float g_qabs[64L * 1024 * 512];      // 128 MB  q_abs; reused for y_c
__device__ float g_logits[64L * 1024 * 1024];   // 256 MB  logits -> P (in place)

// ---------------- generic tiled fp32 GEMM ------------------------------------
// C[M,N] = (ACC ? C : 0) + op(A)[M,K] * op(B)[K,N]
//   TA=false: A[m*lda + k]     TA=true:  A[k*lda + m]
//   TB=false: B[k*ldb + n]     TB=true:  B[n*ldb + k]
// Batch: z = blockIdx.z; zq = z/zdiv; zr = z%zdiv; each base += zq*s?q + zr*s?r
// Requires M,N multiples of 64 and K multiple of 16 (true for all call sites).
template <bool TA, bool TB, bool ACC>
__global__ void gemm64(const float* __restrict__ A, const float* __restrict__ B,
                       float* __restrict__ C, int M, int N, int K,
                       int lda, int ldb, int ldc,
                       long long sAq, long long sAr, long long sBq, long long sBr,
                       long long sCq, long long sCr, int zdiv) {
    int z = blockIdx.z;
    int zq = z / zdiv, zr = z % zdiv;
    A += (long long)zq * sAq + (long long)zr * sAr;
    B += (long long)zq * sBq + (long long)zr * sBr;
    C += (long long)zq * sCq + (long long)zr * sCr;

    const int m0 = blockIdx.y * 64;
    const int n0 = blockIdx.x * 64;

    __shared__ float As[16][68];  // pad to 68 to soften STS bank conflicts
    __shared__ float Bs[16][68];

    const int tid = threadIdx.x;           // 256 threads
    const int row = (tid >> 4) * 4;        // 0..60
    const int col = (tid & 15) * 4;        // 0..60

    float acc[4][4] = {};

    for (int k0 = 0; k0 < K; k0 += 16) {
#pragma unroll
        for (int i = 0; i < 4; i++) {
            int idx = tid + i * 256;       // 0..1023
            if (!TA) {
                int kk = idx & 15, mm = idx >> 4;
                As[kk][mm] = A[(long long)(m0 + mm) * lda + (k0 + kk)];
            } else {
                int mm = idx & 63, kk = idx >> 6;
                As[kk][mm] = A[(long long)(k0 + kk) * lda + (m0 + mm)];
            }
            if (!TB) {
                int nn = idx & 63, kk = idx >> 6;
                Bs[kk][nn] = B[(long long)(k0 + kk) * ldb + (n0 + nn)];
            } else {
                int kk = idx & 15, nn = idx >> 4;
                Bs[kk][nn] = B[(long long)(n0 + nn) * ldb + (k0 + kk)];
            }
        }
        __syncthreads();
#pragma unroll
        for (int kk = 0; kk < 16; kk++) {
            float4 a = *reinterpret_cast<const float4*>(&As[kk][row]);
            float4 b = *reinterpret_cast<const float4*>(&Bs[kk][col]);
            acc[0][0] += a.x * b.x; acc[0][1] += a.x * b.y; acc[0][2] += a.x * b.z; acc[0][3] += a.x * b.w;
            acc[1][0] += a.y * b.x; acc[1][1] += a.y * b.y; acc[1][2] += a.y * b.z; acc[1][3] += a.y * b.w;
            acc[2][0] += a.z * b.x; acc[2][1] += a.z * b.y; acc[2][2] += a.z * b.z; acc[2][3] += a.z * b.w;
            acc[3][0] += a.w * b.x; acc[3][1] += a.w * b.y; acc[3][2] += a.w * b.z; acc[3][3] += a.w * b.w;
        }
        __syncthreads();
    }

#pragma unroll
    for (int i = 0; i < 4; i++) {
        long long off = (long long)(m0 + row + i) * ldc + (n0 + col);
        float4 v = make_float4(acc[i][0], acc[i][1], acc[i][2], acc[i][3]);
        if (ACC) {
            float4 o = *reinterpret_cast<const float4*>(&C[off]);
            v.x += o.x; v.y += o.y; v.z += o.z; v.w += o.w;
        }
        *reinterpret_cast<float4*>(&C[off]) = v;
    }
}

// ---------------- rope --------------------------------------------------------
__global__ void rope_q_kernel(const float* __restrict__ cqr,
                              const float* __restrict__ fc,
                              const float* __restrict__ fs,
                              float* __restrict__ qr) {
    int idx = blockIdx.x * blockDim.x + threadIdx.x;  // B*T*NH*32 = 2097152
    if (idx >= 4 * 1024 * 16 * 32) return;
    int j = idx & 31;
    int h = (idx >> 5) & 15;
    int t = (idx >> 9) & 1023;
    int b = idx >> 19;
    long long base = (((long long)(b * 1024 + t)) * 16 + h) * 64 + 2 * j;
    float re = cqr[base], im = cqr[base + 1];
    float c = fc[t * 32 + j], s = fs[t * 32 + j];
    qr[base]     = re * c - im * s;
    qr[base + 1] = re * s + im * c;
}

__global__ void rope_k_kernel(const float* __restrict__ ckr,
                              const float* __restrict__ fc,
                              const float* __restrict__ fs,
                              float* __restrict__ kr) {
    int idx = blockIdx.x * blockDim.x + threadIdx.x;  // B*T*32 = 131072
    if (idx >= 4 * 1024 * 32) return;
    int j = idx & 31;
    int t = (idx >> 5) & 1023;
    int b = idx >> 15;
    long long base = ((long long)(b * 1024 + t)) * 64 + 2 * j;
    float re = ckr[base], im = ckr[base + 1];
    float c = fc[t * 32 + j], s = fs[t * 32 + j];
    kr[base]     = re * c - im * s;
    kr[base + 1] = re * s + im * c;
}

// ---------------- softmax (in place: logits -> probabilities) -----------------
__global__ void softmax_kernel(float* __restrict__ L) {
    const int r = blockIdx.x;           // (b*NH + h)*T + t
    const int t = r & 1023;
    float* row = L + (long long)r * 1024;
    const float scale = 0.07216878364870323f;  // 1/sqrt(192)
    const int tid = threadIdx.x;        // 128
    __shared__ float red[128];

    float m = -INFINITY;
    for (int s = tid; s <= t; s += 128) m = fmaxf(m, row[s]);
    red[tid] = m;
    __syncthreads();
    for (int o = 64; o; o >>= 1) {
        if (tid < o) red[tid] = fmaxf(red[tid], red[tid + o]);
        __syncthreads();
    }
    m = red[0] * scale;
    __syncthreads();

    float sum = 0.0f;
    for (int s = tid; s <= t; s += 128) sum += __expf(row[s] * scale - m);
    red[tid] = sum;
    __syncthreads();
    for (int o = 64; o; o >>= 1) {
        if (tid < o) red[tid] += red[tid + o];
        __syncthreads();
    }
    float inv = 1.0f / red[0];
    __syncthreads();

    for (int s = tid; s < 1024; s += 128)
        row[s] = (s <= t) ? __expf(row[s] * scale - m) * inv : 0.0f;
}

// ---------------- launcher ----------------------------------------------------
extern "C" void kernel_launch(void* const* d_in, const int* in_sizes, int n_in,
                              void* d_out, int out_size) {
    (void)in_sizes; (void)n_in; (void)out_size;
    const float* x     = (const float*)d_in[0];
    const float* W_dq  = (const float*)d_in[1];
    const float* W_uq  = (const float*)d_in[2];
    const float* W_dkv = (const float*)d_in[3];
    const float* W_uk  = (const float*)d_in[4];
    const float* W_uv  = (const float*)d_in[5];
    const float* W_o   = (const float*)d_in[6];
    const float* W_qr  = (const float*)d_in[7];
    const float* W_kr  = (const float*)d_in[8];
    const float* fc    = (const float*)d_in[9];
    const float* fs    = (const float*)d_in[10];
    float* out = (float*)d_out;

    float *keff, *Mm, *cq, *ckv, *ckr, *cqr, *qr, *kr, *qabs, *logits;
    cudaGetSymbolAddress((void**)&keff,   g_keff);
    cudaGetSymbolAddress((void**)&Mm,     g_M);
    cudaGetSymbolAddress((void**)&cq,     g_cq);
    cudaGetSymbolAddress((void**)&ckv,    g_ckv);
    cudaGetSymbolAddress((void**)&ckr,    g_ckr);
    cudaGetSymbolAddress((void**)&cqr,    g_cqr);
    cudaGetSymbolAddress((void**)&qr,     g_qr);
    cudaGetSymbolAddress((void**)&kr,     g_kr);
    cudaGetSymbolAddress((void**)&qabs,   g_qabs);
    cudaGetSymbolAddress((void**)&logits, g_logits);

    dim3 blk(256);

    // 1) k_eff[h] (512x512) = Wuq_slice(512x128) * Wuk_slice(128x512), 16 heads
    gemm64<false, false, false><<<dim3(8, 8, 16), blk>>>(
        W_uq, W_uk, keff, 512, 512, 128, 2048, 512, 512,
        128, 0, 128LL * 512, 0, 512LL * 512, 0, 1);

    // 2) M (512x2048) = W_uv^T * W_o^T   (M[a][b] = sum_c W_uv[c][a]*W_o[b][c])
    gemm64<true, true, false><<<dim3(32, 8, 1), blk>>>(
        W_uv, W_o, Mm, 512, 2048, 2048, 512, 2048, 2048,
        0, 0, 0, 0, 0, 0, 1);

    // 3) c_q (4096x512) = x * W_dq^T
    gemm64<false, true, false><<<dim3(8, 64, 1), blk>>>(
        x, W_dq, cq, 4096, 512, 2048, 2048, 2048, 512,
        0, 0, 0, 0, 0, 0, 1);

    // 4) c_kv (4096x512) = x * W_dkv^T
    gemm64<false, true, false><<<dim3(8, 64, 1), blk>>>(
        x, W_dkv, ckv, 4096, 512, 2048, 2048, 2048, 512,
        0, 0, 0, 0, 0, 0, 1);

    // 5) c_kr (4096x64) = x * W_kr^T
    gemm64<false, true, false><<<dim3(1, 64, 1), blk>>>(
        x, W_kr, ckr, 4096, 64, 2048, 2048, 2048, 64,
        0, 0, 0, 0, 0, 0, 1);

    // 6) c_qr (4096x1024) = c_q * W_qr^T
    gemm64<false, true, false><<<dim3(16, 64, 1), blk>>>(
        cq, W_qr, cqr, 4096, 1024, 512, 512, 512, 1024,
        0, 0, 0, 0, 0, 0, 1);

    // 7) rope
    rope_q_kernel<<<8192, 256>>>(cqr, fc, fs, qr);
    rope_k_kernel<<<512, 256>>>(ckr, fc, fs, kr);

    // 8) q_abs[b,h] (1024x512) = c_q[b] * k_eff[h]   (z = b*16 + h)
    gemm64<false, false, false><<<dim3(8, 16, 64), blk>>>(
        cq, keff, qabs, 1024, 512, 512, 512, 512, 512,
        1024LL * 512, 0, 0, 512LL * 512,
        16LL * 1024 * 512, 1024LL * 512, 16);

    // 9) logits[b,h] (1024x1024) = q_abs[b,h] * c_kv[b]^T
    gemm64<false, true, false><<<dim3(16, 16, 64), blk>>>(
        qabs, ckv, logits, 1024, 1024, 512, 512, 512, 1024,
        16LL * 1024 * 512, 1024LL * 512, 1024LL * 512, 0,
        16LL * 1024 * 1024, 1024LL * 1024, 16);

    // 10) logits[b,h] += q_r[b,:,h,:] * k_r[b]^T   (K = 64)
    gemm64<false, true, true><<<dim3(16, 16, 64), blk>>>(
        qr, kr, logits, 1024, 1024, 64, 1024, 64, 1024,
        1024LL * 1024, 64, 1024LL * 64, 0,
        16LL * 1024 * 1024, 1024LL * 1024, 16);

    // 11) softmax rows (scale + causal mask + normalize), in place
    softmax_kernel<<<65536, 128>>>(logits);

    // 12) y_c[b,h] (1024x512) = P[b,h] * c_kv[b]   (reuse qabs buffer)
    gemm64<false, false, false><<<dim3(8, 16, 64), blk>>>(
        logits, ckv, qabs, 1024, 512, 1024, 1024, 512, 512,
        16LL * 1024 * 1024, 1024LL * 1024, 1024LL * 512, 0,
        16LL * 1024 * 512, 1024LL * 512, 16);

    // 13) out[b,:,h*128:(h+1)*128] = y_c[b,h] * M[:, h*128:(h+1)*128]
    gemm64<false, false, false><<<dim3(2, 16, 64), blk>>>(
        qabs, Mm, out, 1024, 128, 512, 512, 2048, 2048,
        16LL * 1024 * 512, 1024LL * 512, 0, 128,
        1024LL * 2048, 128, 16);
}

// round 2
// speedup vs baseline: 1.1870x; 1.1870x over previous
#include <cuda_runtime.h>
#include <math.h>

// B=4, T=1024, C=2048, NH=16, HS=128, NLQ=512, NLKV=512, DHR=64
// scale = 1/sqrt(192)

// ---------------- scratch (device globals) ------------------------------------
__device__ float g_keff[16L * 512 * 512];        //  16 MB  k_eff[h][q][k]
__device__ float g_M[512L * 2048];               //   4 MB  M = W_uv^T @ W_o^T
__device__ float g_cq[4096L * 512];              //   8 MB  c_q
__device__ float g_ckr[4096L * 64];              //   1 MB  c_kr (pre-rope)
__device__ float g_cqr[4096L * 1024];            //  16 MB  c_qr (pre-rope)
__device__ float g_qcat[64L * 1024 * 576];       // 151 MB  [q_abs | q_r]; reused for y_c
__device__ float g_kcat[4096L * 576];            // 9.4 MB  [c_kv | k_r]
__device__ float g_logits[64L * 1024 * 1024];    // 256 MB  logits -> P (in place)

// ---------------- tf32 helpers -------------------------------------------------
__device__ __forceinline__ unsigned f2tf(float f) {
    unsigned u;
    asm("cvt.rna.tf32.f32 %0, %1;" : "=r"(u) : "f"(f));
    return u;
}

__device__ __forceinline__ void mma_tf32(float* c, const unsigned* a, const unsigned* b) {
    asm volatile(
        "mma.sync.aligned.m16n8k8.row.col.f32.tf32.tf32.f32 "
        "{%0,%1,%2,%3}, {%4,%5,%6,%7}, {%8,%9}, {%0,%1,%2,%3};"
        : "+f"(c[0]), "+f"(c[1]), "+f"(c[2]), "+f"(c[3])
        : "r"(a[0]), "r"(a[1]), "r"(a[2]), "r"(a[3]), "r"(b[0]), "r"(b[1]));
}

// ---------------- tf32 tensor-core GEMM ----------------------------------------
// C[M,N] = op(A)[M,K] * op(B)[K,N]
// TA=false: A[m*lda+k]  TA=true: A[k*lda+m]
// TB=false: B[k*ldb+n]  TB=true: B[n*ldb+k]
// Tiles: BM=128, BN=64, BK=32. 256 threads (8 warps, 4x2 of 32x32 warp tiles).
// Requires M%128==0, N%64==0, K%32==0 (all call sites satisfy this).
template <bool TA, bool TB>
__global__ void __launch_bounds__(256) gemm_tc(
        const float* __restrict__ A, const float* __restrict__ B,
        float* __restrict__ C, int M, int N, int K,
        int lda, int ldb, int ldc,
        long long sAq, long long sAr, long long sBq, long long sBr,
        long long sCq, long long sCr, int zdiv) {
    int z = blockIdx.z;
    int zq = z / zdiv, zr = z % zdiv;
    A += (long long)zq * sAq + (long long)zr * sAr;
    B += (long long)zq * sBq + (long long)zr * sBr;
    C += (long long)zq * sCq + (long long)zr * sCr;

    const int m0 = blockIdx.y * 128;
    const int n0 = blockIdx.x * 64;

    __shared__ unsigned As[32 * 136];  // As[k][m], stride 136 -> frag LDS conflict-free
    __shared__ unsigned Bs[32 * 72];   // Bs[k][n], stride 72

    const int tid  = threadIdx.x;
    const int lane = tid & 31;
    const int warp = tid >> 5;
    const int wm = (warp >> 1) * 32;   // 0,32,64,96
    const int wn = (warp & 1) * 32;    // 0,32
    const int lane4 = lane & 3;
    const int laneg = lane >> 2;

    float acc[2][4][4] = {};

    for (int k0 = 0; k0 < K; k0 += 32) {
        // ---- load A tile (128x32) ----
        if (!TA) {
#pragma unroll
            for (int i = 0; i < 4; i++) {
                int idx = tid + i * 256;          // 0..1023
                int m = idx >> 3, c4 = idx & 7;   // 8 float4 per row
                float4 v = *reinterpret_cast<const float4*>(
                    &A[(long long)(m0 + m) * lda + k0 + c4 * 4]);
                As[(c4 * 4 + 0) * 136 + m] = f2tf(v.x);
                As[(c4 * 4 + 1) * 136 + m] = f2tf(v.y);
                As[(c4 * 4 + 2) * 136 + m] = f2tf(v.z);
                As[(c4 * 4 + 3) * 136 + m] = f2tf(v.w);
            }
        } else {
#pragma unroll
            for (int i = 0; i < 4; i++) {
                int idx = tid + i * 256;
                int k = idx >> 5, c4 = idx & 31;  // 32 float4 per row of 128
                float4 v = *reinterpret_cast<const float4*>(
                    &A[(long long)(k0 + k) * lda + m0 + c4 * 4]);
                unsigned* p = &As[k * 136 + c4 * 4];
                p[0] = f2tf(v.x); p[1] = f2tf(v.y); p[2] = f2tf(v.z); p[3] = f2tf(v.w);
            }
        }
        // ---- load B tile (32x64) ----
        if (!TB) {
#pragma unroll
            for (int i = 0; i < 2; i++) {
                int idx = tid + i * 256;          // 0..511
                int k = idx >> 4, c4 = idx & 15;  // 16 float4 per row of 64
                float4 v = *reinterpret_cast<const float4*>(
                    &B[(long long)(k0 + k) * ldb + n0 + c4 * 4]);
                unsigned* p = &Bs[k * 72 + c4 * 4];
                p[0] = f2tf(v.x); p[1] = f2tf(v.y); p[2] = f2tf(v.z); p[3] = f2tf(v.w);
            }
        } else {
#pragma unroll
            for (int i = 0; i < 2; i++) {
                int idx = tid + i * 256;
                int n = idx >> 3, c4 = idx & 7;   // 8 float4 per row of 32
                float4 v = *reinterpret_cast<const float4*>(
                    &B[(long long)(n0 + n) * ldb + k0 + c4 * 4]);
                Bs[(c4 * 4 + 0) * 72 + n] = f2tf(v.x);
                Bs[(c4 * 4 + 1) * 72 + n] = f2tf(v.y);
                Bs[(c4 * 4 + 2) * 72 + n] = f2tf(v.z);
                Bs[(c4 * 4 + 3) * 72 + n] = f2tf(v.w);
            }
        }
        __syncthreads();

        // ---- compute ----
#pragma unroll
        for (int kk = 0; kk < 32; kk += 8) {
            int k1 = kk + lane4, k2 = k1 + 4;
            unsigned a[2][4], b[4][2];
#pragma unroll
            for (int mi = 0; mi < 2; mi++) {
                int mr = wm + mi * 16 + laneg;
                a[mi][0] = As[k1 * 136 + mr];
                a[mi][1] = As[k1 * 136 + mr + 8];
                a[mi][2] = As[k2 * 136 + mr];
                a[mi][3] = As[k2 * 136 + mr + 8];
            }
#pragma unroll
            for (int ni = 0; ni < 4; ni++) {
                int nc = wn + ni * 8 + laneg;
                b[ni][0] = Bs[k1 * 72 + nc];
                b[ni][1] = Bs[k2 * 72 + nc];
            }
#pragma unroll
            for (int mi = 0; mi < 2; mi++)
#pragma unroll
                for (int ni = 0; ni < 4; ni++)
                    mma_tf32(acc[mi][ni], a[mi], b[ni]);
        }
        __syncthreads();
    }

    // ---- epilogue ----
#pragma unroll
    for (int mi = 0; mi < 2; mi++) {
#pragma unroll
        for (int ni = 0; ni < 4; ni++) {
            int row = m0 + wm + mi * 16 + laneg;
            int col = n0 + wn + ni * 8 + lane4 * 2;
            *reinterpret_cast<float2*>(&C[(long long)row * ldc + col]) =
                make_float2(acc[mi][ni][0], acc[mi][ni][1]);
            *reinterpret_cast<float2*>(&C[(long long)(row + 8) * ldc + col]) =
                make_float2(acc[mi][ni][2], acc[mi][ni][3]);
        }
    }
}

// ---------------- rope (writes into concat buffers) ----------------------------
__global__ void rope_q_kernel(const float* __restrict__ cqr,
                              const float* __restrict__ fc,
                              const float* __restrict__ fs,
                              float* __restrict__ qcat) {
    int idx = blockIdx.x * blockDim.x + threadIdx.x;  // B*T*NH*32
    if (idx >= 4 * 1024 * 16 * 32) return;
    int j = idx & 31;
    int h = (idx >> 5) & 15;
    int t = (idx >> 9) & 1023;
    int b = idx >> 19;
    long long src = (((long long)(b * 1024 + t)) * 1024) + h * 64 + 2 * j;
    float re = cqr[src], im = cqr[src + 1];
    float c = fc[t * 32 + j], s = fs[t * 32 + j];
    long long dst = (((long long)(b * 16 + h)) * 1024 + t) * 576 + 512 + 2 * j;
    qcat[dst]     = re * c - im * s;
    qcat[dst + 1] = re * s + im * c;
}

__global__ void rope_k_kernel(const float* __restrict__ ckr,
                              const float* __restrict__ fc,
                              const float* __restrict__ fs,
                              float* __restrict__ kcat) {
    int idx = blockIdx.x * blockDim.x + threadIdx.x;  // B*T*32
    if (idx >= 4 * 1024 * 32) return;
    int j = idx & 31;
    int t = (idx >> 5) & 1023;
    int b = idx >> 15;
    long long src = ((long long)(b * 1024 + t)) * 64 + 2 * j;
    float re = ckr[src], im = ckr[src + 1];
    float c = fc[t * 32 + j], s = fs[t * 32 + j];
    long long dst = ((long long)(b * 1024 + t)) * 576 + 512 + 2 * j;
    kcat[dst]     = re * c - im * s;
    kcat[dst + 1] = re * s + im * c;
}

// ---------------- softmax (in place) -------------------------------------------
__global__ void softmax_kernel(float* __restrict__ L) {
    const int r = blockIdx.x;           // (b*NH + h)*T + t
    const int t = r & 1023;
    float* row = L + (long long)r * 1024;
    const float scale = 0.07216878364870323f;
    const int tid = threadIdx.x;        // 128
    __shared__ float red[128];

    float m = -INFINITY;
    for (int s = tid; s <= t; s += 128) m = fmaxf(m, row[s]);
    red[tid] = m;
    __syncthreads();
    for (int o = 64; o; o >>= 1) {
        if (tid < o) red[tid] = fmaxf(red[tid], red[tid + o]);
        __syncthreads();
    }
    m = red[0] * scale;
    __syncthreads();

    float sum = 0.0f;
    for (int s = tid; s <= t; s += 128) sum += __expf(row[s] * scale - m);
    red[tid] = sum;
    __syncthreads();
    for (int o = 64; o; o >>= 1) {
        if (tid < o) red[tid] += red[tid + o];
        __syncthreads();
    }
    float inv = 1.0f / red[0];
    __syncthreads();

    for (int s = tid; s < 1024; s += 128)
        row[s] = (s <= t) ? __expf(row[s] * scale - m) * inv : 0.0f;
}

// ---------------- launcher ------------------------------------------------------
extern "C" void kernel_launch(void* const* d_in, const int* in_sizes, int n_in,
                              void* d_out, int out_size) {
    (void)in_sizes; (void)n_in; (void)out_size;
    const float* x     = (const float*)d_in[0];
    const float* W_dq  = (const float*)d_in[1];
    const float* W_uq  = (const float*)d_in[2];
    const float* W_dkv = (const float*)d_in[3];
    const float* W_uk  = (const float*)d_in[4];
    const float* W_uv  = (const float*)d_in[5];
    const float* W_o   = (const float*)d_in[6];
    const float* W_qr  = (const float*)d_in[7];
    const float* W_kr  = (const float*)d_in[8];
    const float* fc    = (const float*)d_in[9];
    const float* fs    = (const float*)d_in[10];
    float* out = (float*)d_out;

    float *keff, *Mm, *cq, *ckr, *cqr, *qcat, *kcat, *logits;
    cudaGetSymbolAddress((void**)&keff,   g_keff);
    cudaGetSymbolAddress((void**)&Mm,     g_M);
    cudaGetSymbolAddress((void**)&cq,     g_cq);
    cudaGetSymbolAddress((void**)&ckr,    g_ckr);
    cudaGetSymbolAddress((void**)&cqr,    g_cqr);
    cudaGetSymbolAddress((void**)&qcat,   g_qcat);
    cudaGetSymbolAddress((void**)&kcat,   g_kcat);
    cudaGetSymbolAddress((void**)&logits, g_logits);

    dim3 blk(256);
    const long long QZ = 1024LL * 576;   // per-(b,h) stride in qcat
    const long long KZ = 1024LL * 576;   // per-b stride in kcat
    const long long LZ = 1024LL * 1024;  // per-(b,h) stride in logits
    const long long YZ = 1024LL * 512;   // per-(b,h) stride in y (reuses qcat)

    // 1) k_eff[h] (512x512) = Wuq_slice(512x128) @ Wuk_slice(128x512)
    gemm_tc<false, false><<<dim3(8, 4, 16), blk>>>(
        W_uq, W_uk, keff, 512, 512, 128, 2048, 512, 512,
        128, 0, 128LL * 512, 0, 512LL * 512, 0, 1);

    // 2) M (512x2048) = W_uv^T @ W_o^T
    gemm_tc<true, true><<<dim3(32, 4, 1), blk>>>(
        W_uv, W_o, Mm, 512, 2048, 2048, 512, 2048, 2048,
        0, 0, 0, 0, 0, 0, 1);

    // 3) c_q (4096x512) = x @ W_dq^T
    gemm_tc<false, true><<<dim3(8, 32, 1), blk>>>(
        x, W_dq, cq, 4096, 512, 2048, 2048, 2048, 512,
        0, 0, 0, 0, 0, 0, 1);

    // 4) c_kv -> kcat[:, 0:512] (4096x512) = x @ W_dkv^T
    gemm_tc<false, true><<<dim3(8, 32, 1), blk>>>(
        x, W_dkv, kcat, 4096, 512, 2048, 2048, 2048, 576,
        0, 0, 0, 0, 0, 0, 1);

    // 5) c_kr (4096x64) = x @ W_kr^T
    gemm_tc<false, true><<<dim3(1, 32, 1), blk>>>(
        x, W_kr, ckr, 4096, 64, 2048, 2048, 2048, 64,
        0, 0, 0, 0, 0, 0, 1);

    // 6) c_qr (4096x1024) = c_q @ W_qr^T
    gemm_tc<false, true><<<dim3(16, 32, 1), blk>>>(
        cq, W_qr, cqr, 4096, 1024, 512, 512, 512, 1024,
        0, 0, 0, 0, 0, 0, 1);

    // 7) rope into concat tails
    rope_q_kernel<<<8192, 256>>>(cqr, fc, fs, qcat);
    rope_k_kernel<<<512, 256>>>(ckr, fc, fs, kcat);

    // 8) q_abs -> qcat[:, 0:512]: (1024x512) = c_q[b] @ k_eff[h], z=b*16+h
    gemm_tc<false, false><<<dim3(8, 8, 64), blk>>>(
        cq, keff, qcat, 1024, 512, 512, 512, 512, 576,
        1024LL * 512, 0, 0, 512LL * 512,
        16LL * QZ, QZ, 16);

    // 9) logits[b,h] (1024x1024) = qcat[b,h] @ kcat[b]^T  (K=576: content + rope)
    gemm_tc<false, true><<<dim3(16, 8, 64), blk>>>(
        qcat, kcat, logits, 1024, 1024, 576, 576, 576, 1024,
        16LL * QZ, QZ, KZ, 0,
        16LL * LZ, LZ, 16);

    // 10) softmax rows (scale + causal mask), in place
    softmax_kernel<<<65536, 128>>>(logits);

    // 11) y_c[b,h] (1024x512) = P[b,h] @ kcat[b][:, 0:512]   (reuse qcat buffer)
    gemm_tc<false, false><<<dim3(8, 8, 64), blk>>>(
        logits, kcat, qcat, 1024, 512, 1024, 1024, 576, 512,
        16LL * LZ, LZ, KZ, 0,
        16LL * YZ, YZ, 16);

    // 12) out[b, :, h*128:(h+1)*128] = y_c[b,h] @ M[:, h*128:(h+1)*128]
    gemm_tc<false, false><<<dim3(2, 8, 64), blk>>>(
        qcat, Mm, out, 1024, 128, 512, 512, 2048, 2048,
        16LL * YZ, YZ, 0, 128,
        1024LL * 2048, 128, 16);
}

// round 3
// speedup vs baseline: 2.7945x; 2.3542x over previous
#include <cuda_runtime.h>
#include <math.h>

// B=4, T=1024, C=2048, NH=16, HS=128, NLQ=512, NLKV=512, DHR=64
// scale = 1/sqrt(192)

// ---------------- scratch (device globals) ------------------------------------
__device__ float g_keff[16L * 512 * 512];        //  16 MB  k_eff[h][q][k]
__device__ float g_M[512L * 2048];               //   4 MB  M = W_uv^T @ W_o^T
__device__ float g_wcat[640L * 2048];            //   5 MB  [W_dq ; W_kr ; zero-pad]
__device__ float g_cqx[4096L * 640];             //  10 MB  [c_q | c_kr | pad]
__device__ float g_cqr[4096L * 1024];            //  16 MB  c_qr (pre-rope)
__device__ float g_qcat[64L * 1024 * 576];       // 151 MB  [q_abs | q_r]; reused for y_c
__device__ float g_kcat[4096L * 576];            // 9.4 MB  [c_kv | k_r]
__device__ float g_logits[64L * 1024 * 1024];    // 256 MB  logits -> P (in place)

// ---------------- tf32 helpers -------------------------------------------------
__device__ __forceinline__ unsigned f2tf(float f) {
    unsigned u;
    asm("cvt.rna.tf32.f32 %0, %1;" : "=r"(u) : "f"(f));
    return u;
}

__device__ __forceinline__ void mma_tf32(float* c, const unsigned* a, const unsigned* b) {
    asm volatile(
        "mma.sync.aligned.m16n8k8.row.col.f32.tf32.tf32.f32 "
        "{%0,%1,%2,%3}, {%4,%5,%6,%7}, {%8,%9}, {%0,%1,%2,%3};"
        : "+f"(c[0]), "+f"(c[1]), "+f"(c[2]), "+f"(c[3])
        : "r"(a[0]), "r"(a[1]), "r"(a[2]), "r"(a[3]), "r"(b[0]), "r"(b[1]));
}

// ---------------- tf32 tensor-core GEMM v2 -------------------------------------
// Block tile 256(M) x 128(N) x 32(K). 256 threads = 8 warps as 4(m) x 2(n),
// each warp computes a 64x64 tile (4 x m16 tiles, 8 x n8 tiles).
// Double-buffered dynamic smem (100KB) with register-staged gmem prefetch.
// MODE: 0 = plain, 1 = causal tile-skip (for logits), 2 = causal K-limit (PV).
// Requires M%256==0, N%128==0, K%32==0.
#define SA 264           // A smem row stride (words): 256 + 8, mod 32 == 8 (CF)
#define SB 136           // B smem row stride: 128 + 8, mod 32 == 8 (CF)
#define ASZ (32 * SA)    // 8448 words
#define BSZ (32 * SB)    // 4352 words
#define BUFSZ (ASZ + BSZ)
#define SMEM_BYTES (2 * BUFSZ * 4)   // 102400 B

template <bool TA, bool TB, int MODE>
__global__ void __launch_bounds__(256) gemm_tc2(
        const float* __restrict__ A, const float* __restrict__ B,
        float* __restrict__ C, int M, int N, int K,
        int lda, int ldb, int ldc,
        long long sAq, long long sAr, long long sBq, long long sBr,
        long long sCq, long long sCr, int zdiv) {
    const int m0 = blockIdx.y * 256;
    const int n0 = blockIdx.x * 128;
    if (MODE == 1 && n0 >= m0 + 256) return;   // fully-masked causal tile

    int z = blockIdx.z;
    int zq = z / zdiv, zr = z % zdiv;
    A += (long long)zq * sAq + (long long)zr * sAr;
    B += (long long)zq * sBq + (long long)zr * sBr;
    C += (long long)zq * sCq + (long long)zr * sCr;

    int Keff = (MODE == 2) ? ((m0 + 256 < K) ? m0 + 256 : K) : K;
    const int ntiles = Keff >> 5;

    extern __shared__ unsigned sh[];

    const int tid  = threadIdx.x;
    const int lane = tid & 31;
    const int warp = tid >> 5;
    const int wm = (warp >> 1) * 64;   // 0,64,128,192
    const int wn = (warp & 1) * 64;    // 0,64
    const int lane4 = lane & 3;
    const int laneg = lane >> 2;

    float acc[4][8][4] = {};
    float4 ar[8], br[4];

    // ---- gmem -> regs staging ----
    auto load_regs = [&](int k0) {
        if (!TA) {
            const float* p = A + (long long)(m0 + tid) * lda + k0;
#pragma unroll
            for (int i = 0; i < 8; i++)
                ar[i] = *reinterpret_cast<const float4*>(p + i * 4);
        } else {
            const float* p = A + (long long)(k0 + (tid >> 3)) * lda + m0 + (tid & 7) * 32;
#pragma unroll
            for (int i = 0; i < 8; i++)
                ar[i] = *reinterpret_cast<const float4*>(p + i * 4);
        }
        if (!TB) {
            const float* p = B + (long long)(k0 + (tid >> 3)) * ldb + n0 + (tid & 7) * 16;
#pragma unroll
            for (int i = 0; i < 4; i++)
                br[i] = *reinterpret_cast<const float4*>(p + i * 4);
        } else {
            const float* p = B + (long long)(n0 + (tid >> 1)) * ldb + k0 + (tid & 1) * 16;
#pragma unroll
            for (int i = 0; i < 4; i++)
                br[i] = *reinterpret_cast<const float4*>(p + i * 4);
        }
    };

    // ---- regs -> smem (with tf32 round) ----
    auto store_smem = [&](int buf) {
        unsigned* As = sh + buf * BUFSZ;
        unsigned* Bs = As + ASZ;
        if (!TA) {
            // ar[i] holds k = i*4 .. i*4+3 for row tid -> scatter STS.32 (CF)
#pragma unroll
            for (int i = 0; i < 8; i++) {
                As[(i * 4 + 0) * SA + tid] = f2tf(ar[i].x);
                As[(i * 4 + 1) * SA + tid] = f2tf(ar[i].y);
                As[(i * 4 + 2) * SA + tid] = f2tf(ar[i].z);
                As[(i * 4 + 3) * SA + tid] = f2tf(ar[i].w);
            }
        } else {
            // row k = tid>>3, 32 consecutive m -> STS.128
            unsigned* p = As + (tid >> 3) * SA + (tid & 7) * 32;
#pragma unroll
            for (int i = 0; i < 8; i++) {
                uint4 v = make_uint4(f2tf(ar[i].x), f2tf(ar[i].y), f2tf(ar[i].z), f2tf(ar[i].w));
                *reinterpret_cast<uint4*>(p + i * 4) = v;
            }
        }
        if (!TB) {
            unsigned* p = Bs + (tid >> 3) * SB + (tid & 7) * 16;
#pragma unroll
            for (int i = 0; i < 4; i++) {
                uint4 v = make_uint4(f2tf(br[i].x), f2tf(br[i].y), f2tf(br[i].z), f2tf(br[i].w));
                *reinterpret_cast<uint4*>(p + i * 4) = v;
            }
        } else {
            int n = tid >> 1, kh = (tid & 1) * 16;
#pragma unroll
            for (int i = 0; i < 4; i++) {
                Bs[(kh + i * 4 + 0) * SB + n] = f2tf(br[i].x);
                Bs[(kh + i * 4 + 1) * SB + n] = f2tf(br[i].y);
                Bs[(kh + i * 4 + 2) * SB + n] = f2tf(br[i].z);
                Bs[(kh + i * 4 + 3) * SB + n] = f2tf(br[i].w);
            }
        }
    };

    load_regs(0);
    store_smem(0);
    __syncthreads();

    for (int t = 0; t < ntiles; t++) {
        const unsigned* As = sh + (t & 1) * BUFSZ;
        const unsigned* Bs = As + ASZ;
        if (t + 1 < ntiles) load_regs((t + 1) << 5);

#pragma unroll
        for (int kk = 0; kk < 32; kk += 8) {
            int k1 = kk + lane4, k2 = k1 + 4;
            unsigned a[4][4], b[8][2];
#pragma unroll
            for (int mi = 0; mi < 4; mi++) {
                int mr = wm + mi * 16 + laneg;
                a[mi][0] = As[k1 * SA + mr];
                a[mi][1] = As[k1 * SA + mr + 8];
                a[mi][2] = As[k2 * SA + mr];
                a[mi][3] = As[k2 * SA + mr + 8];
            }
#pragma unroll
            for (int ni = 0; ni < 8; ni++) {
                int nc = wn + ni * 8 + laneg;
                b[ni][0] = Bs[k1 * SB + nc];
                b[ni][1] = Bs[k2 * SB + nc];
            }
#pragma unroll
            for (int mi = 0; mi < 4; mi++)
#pragma unroll
                for (int ni = 0; ni < 8; ni++)
                    mma_tf32(acc[mi][ni], a[mi], b[ni]);
        }

        if (t + 1 < ntiles) store_smem((t + 1) & 1);
        __syncthreads();
    }

    // ---- epilogue ----
#pragma unroll
    for (int mi = 0; mi < 4; mi++) {
#pragma unroll
        for (int ni = 0; ni < 8; ni++) {
            int row = m0 + wm + mi * 16 + laneg;
            int col = n0 + wn + ni * 8 + lane4 * 2;
            *reinterpret_cast<float2*>(&C[(long long)row * ldc + col]) =
                make_float2(acc[mi][ni][0], acc[mi][ni][1]);
            *reinterpret_cast<float2*>(&C[(long long)(row + 8) * ldc + col]) =
                make_float2(acc[mi][ni][2], acc[mi][ni][3]);
        }
    }
}

// ---------------- weight concat: Wcat = [W_dq(512) ; W_kr(64) ; pad(64)] -------
__global__ void build_wcat(const float* __restrict__ Wdq,
                           const float* __restrict__ Wkr,
                           float* __restrict__ Wcat) {
    int idx = blockIdx.x * blockDim.x + threadIdx.x;   // 576*2048 / 4 float4s
    if (idx >= 576 * 512) return;
    int row = idx >> 9;           // /512 float4 per row
    int c4 = idx & 511;
    float4 v = (row < 512)
        ? reinterpret_cast<const float4*>(Wdq)[row * 512 + c4]
        : reinterpret_cast<const float4*>(Wkr)[(row - 512) * 512 + c4];
    reinterpret_cast<float4*>(Wcat)[row * 512 + c4] = v;
}

// ---------------- rope (writes into concat buffers) ----------------------------
__global__ void rope_q_kernel(const float* __restrict__ cqr,
                              const float* __restrict__ fc,
                              const float* __restrict__ fs,
                              float* __restrict__ qcat) {
    int idx = blockIdx.x * blockDim.x + threadIdx.x;  // B*T*NH*32
    if (idx >= 4 * 1024 * 16 * 32) return;
    int j = idx & 31;
    int h = (idx >> 5) & 15;
    int t = (idx >> 9) & 1023;
    int b = idx >> 19;
    long long src = (((long long)(b * 1024 + t)) * 1024) + h * 64 + 2 * j;
    float re = cqr[src], im = cqr[src + 1];
    float c = fc[t * 32 + j], s = fs[t * 32 + j];
    long long dst = (((long long)(b * 16 + h)) * 1024 + t) * 576 + 512 + 2 * j;
    qcat[dst]     = re * c - im * s;
    qcat[dst + 1] = re * s + im * c;
}

__global__ void rope_k_kernel(const float* __restrict__ cqx,
                              const float* __restrict__ fc,
                              const float* __restrict__ fs,
                              float* __restrict__ kcat) {
    int idx = blockIdx.x * blockDim.x + threadIdx.x;  // B*T*32
    if (idx >= 4 * 1024 * 32) return;
    int j = idx & 31;
    int t = (idx >> 5) & 1023;
    int b = idx >> 15;
    long long src = ((long long)(b * 1024 + t)) * 640 + 512 + 2 * j;  // c_kr cols
    float re = cqx[src], im = cqx[src + 1];
    float c = fc[t * 32 + j], s = fs[t * 32 + j];
    long long dst = ((long long)(b * 1024 + t)) * 576 + 512 + 2 * j;
    kcat[dst]     = re * c - im * s;
    kcat[dst + 1] = re * s + im * c;
}

// ---------------- softmax (in place) -------------------------------------------
__global__ void softmax_kernel(float* __restrict__ L) {
    const int r = blockIdx.x;           // (b*NH + h)*T + t
    const int t = r & 1023;
    float* row = L + (long long)r * 1024;
    const float scale = 0.07216878364870323f;
    const int tid = threadIdx.x;        // 128
    __shared__ float red[128];

    float m = -INFINITY;
    for (int s = tid; s <= t; s += 128) m = fmaxf(m, row[s]);
    red[tid] = m;
    __syncthreads();
    for (int o = 64; o; o >>= 1) {
        if (tid < o) red[tid] = fmaxf(red[tid], red[tid + o]);
        __syncthreads();
    }
    m = red[0] * scale;
    __syncthreads();

    float sum = 0.0f;
    for (int s = tid; s <= t; s += 128) sum += __expf(row[s] * scale - m);
    red[tid] = sum;
    __syncthreads();
    for (int o = 64; o; o >>= 1) {
        if (tid < o) red[tid] += red[tid + o];
        __syncthreads();
    }
    float inv = 1.0f / red[0];
    __syncthreads();

    for (int s = tid; s < 1024; s += 128)
        row[s] = (s <= t) ? __expf(row[s] * scale - m) * inv : 0.0f;
}

// ---------------- launcher ------------------------------------------------------
extern "C" void kernel_launch(void* const* d_in, const int* in_sizes, int n_in,
                              void* d_out, int out_size) {
    (void)in_sizes; (void)n_in; (void)out_size;
    const float* x     = (const float*)d_in[0];
    const float* W_dq  = (const float*)d_in[1];
    const float* W_uq  = (const float*)d_in[2];
    const float* W_dkv = (const float*)d_in[3];
    const float* W_uk  = (const float*)d_in[4];
    const float* W_uv  = (const float*)d_in[5];
    const float* W_o   = (const float*)d_in[6];
    const float* W_qr  = (const float*)d_in[7];
    const float* W_kr  = (const float*)d_in[8];
    const float* fc    = (const float*)d_in[9];
    const float* fs    = (const float*)d_in[10];
    float* out = (float*)d_out;

    float *keff, *Mm, *wcat, *cqx, *cqr, *qcat, *kcat, *logits;
    cudaGetSymbolAddress((void**)&keff,   g_keff);
    cudaGetSymbolAddress((void**)&Mm,     g_M);
    cudaGetSymbolAddress((void**)&wcat,   g_wcat);
    cudaGetSymbolAddress((void**)&cqx,    g_cqx);
    cudaGetSymbolAddress((void**)&cqr,    g_cqr);
    cudaGetSymbolAddress((void**)&qcat,   g_qcat);
    cudaGetSymbolAddress((void**)&kcat,   g_kcat);
    cudaGetSymbolAddress((void**)&logits, g_logits);

    // opt into 100KB dynamic smem (idempotent; ignore errors)
    cudaFuncSetAttribute(gemm_tc2<false, true,  0>, cudaFuncAttributeMaxDynamicSharedMemorySize, SMEM_BYTES);
    cudaFuncSetAttribute(gemm_tc2<false, false, 0>, cudaFuncAttributeMaxDynamicSharedMemorySize, SMEM_BYTES);
    cudaFuncSetAttribute(gemm_tc2<true,  true,  0>, cudaFuncAttributeMaxDynamicSharedMemorySize, SMEM_BYTES);
    cudaFuncSetAttribute(gemm_tc2<false, true,  1>, cudaFuncAttributeMaxDynamicSharedMemorySize, SMEM_BYTES);
    cudaFuncSetAttribute(gemm_tc2<false, false, 2>, cudaFuncAttributeMaxDynamicSharedMemorySize, SMEM_BYTES);

    dim3 blk(256);
    const long long QZ = 1024LL * 576;   // per-(b,h) stride in qcat
    const long long KZ = 1024LL * 576;   // per-b stride in kcat
    const long long LZ = 1024LL * 1024;  // per-(b,h) stride in logits
    const long long YZ = 1024LL * 512;   // per-(b,h) stride in y (reuses qcat)

    // 0) Wcat = [W_dq ; W_kr] (rows 576..639 stay zero from static init)
    build_wcat<<<(576 * 512 + 255) / 256, 256>>>(W_dq, W_kr, wcat);

    // 1) cqx (4096x640) = x @ Wcat^T   (c_q in cols 0..511, c_kr in 512..575)
    gemm_tc2<false, true, 0><<<dim3(5, 16, 1), blk, SMEM_BYTES>>>(
        x, wcat, cqx, 4096, 640, 2048, 2048, 2048, 640,
        0, 0, 0, 0, 0, 0, 1);

    // 2) kcat[:, 0:512] (4096x512) = x @ W_dkv^T
    gemm_tc2<false, true, 0><<<dim3(4, 16, 1), blk, SMEM_BYTES>>>(
        x, W_dkv, kcat, 4096, 512, 2048, 2048, 2048, 576,
        0, 0, 0, 0, 0, 0, 1);

    // 3) k_eff[h] (512x512) = Wuq_slice(512x128) @ Wuk_slice(128x512)
    gemm_tc2<false, false, 0><<<dim3(4, 2, 16), blk, SMEM_BYTES>>>(
        W_uq, W_uk, keff, 512, 512, 128, 2048, 512, 512,
        128, 0, 128LL * 512, 0, 512LL * 512, 0, 1);

    // 4) M (512x2048) = W_uv^T @ W_o^T
    gemm_tc2<true, true, 0><<<dim3(16, 2, 1), blk, SMEM_BYTES>>>(
        W_uv, W_o, Mm, 512, 2048, 2048, 512, 2048, 2048,
        0, 0, 0, 0, 0, 0, 1);

    // 5) c_qr (4096x1024) = c_q @ W_qr^T   (c_q = cqx cols 0..511, lda=640)
    gemm_tc2<false, true, 0><<<dim3(8, 16, 1), blk, SMEM_BYTES>>>(
        cqx, W_qr, cqr, 4096, 1024, 512, 640, 512, 1024,
        0, 0, 0, 0, 0, 0, 1);

    // 6) rope into concat tails
    rope_q_kernel<<<8192, 256>>>(cqr, fc, fs, qcat);
    rope_k_kernel<<<512, 256>>>(cqx, fc, fs, kcat);

    // 7) q_abs -> qcat[:, 0:512]: (1024x512) = c_q[b] @ k_eff[h], z=b*16+h
    gemm_tc2<false, false, 0><<<dim3(4, 4, 64), blk, SMEM_BYTES>>>(
        cqx, keff, qcat, 1024, 512, 512, 640, 512, 576,
        1024LL * 640, 0, 0, 512LL * 512,
        16LL * QZ, QZ, 16);

    // 8) logits[b,h] (1024x1024) = qcat[b,h] @ kcat[b]^T  (K=576), causal skip
    gemm_tc2<false, true, 1><<<dim3(8, 4, 64), blk, SMEM_BYTES>>>(
        qcat, kcat, logits, 1024, 1024, 576, 576, 576, 1024,
        16LL * QZ, QZ, KZ, 0,
        16LL * LZ, LZ, 16);

    // 9) softmax rows (scale + causal mask), in place
    softmax_kernel<<<65536, 128>>>(logits);

    // 10) y_c[b,h] (1024x512) = P[b,h] @ kcat[b][:, 0:512], causal K-limit
    gemm_tc2<false, false, 2><<<dim3(4, 4, 64), blk, SMEM_BYTES>>>(
        logits, kcat, qcat, 1024, 512, 1024, 1024, 576, 512,
        16LL * LZ, LZ, KZ, 0,
        16LL * YZ, YZ, 16);

    // 11) out[b, :, h*128:(h+1)*128] = y_c[b,h] @ M[:, h*128:(h+1)*128]
    gemm_tc2<false, false, 0><<<dim3(1, 4, 64), blk, SMEM_BYTES>>>(
        qcat, Mm, out, 1024, 128, 512, 512, 2048, 2048,
        16LL * YZ, YZ, 0, 128,
        1024LL * 2048, 128, 16);
}

// round 4
// speedup vs baseline: 3.4085x; 1.2197x over previous
#include <cuda_runtime.h>
#include <math.h>

// B=4, T=1024, C=2048, NH=16, HS=128, NLQ=512, NLKV=512, DHR=64
// scale = 1/sqrt(192)

// ---------------- scratch (device globals) ------------------------------------
__device__ float g_keff[16L * 512 * 512];        //  16 MB
__device__ float g_M[512L * 2048];               //   4 MB
__device__ float g_wcat[640L * 2048];            //   5 MB  [W_dq ; W_kr ; pad] (tf32)
__device__ float g_xr[4096L * 2048];             //  32 MB  x rounded to tf32
__device__ float g_wdkv[512L * 2048];            //   4 MB
__device__ float g_wqr[1024L * 512];             //   2 MB
__device__ float g_wuq[2048L * 512];             //   4 MB
__device__ float g_wuk[2048L * 512];             //   4 MB
__device__ float g_wuv[2048L * 512];             //   4 MB
__device__ float g_wo[2048L * 2048];             //  16 MB
__device__ float g_cqx[4096L * 640];             //  10 MB  [c_q | c_kr | pad]
__device__ float g_cqr[4096L * 1024];            //  16 MB
__device__ float g_qcat[64L * 1024 * 576];       // 151 MB  [q_abs | q_r]; reused for y_c
__device__ float g_kcat[4096L * 576];            // 9.4 MB  [c_kv | k_r]
__device__ float g_logits[64L * 1024 * 1024];    // 256 MB  logits -> P (in place)

// ---------------- helpers -------------------------------------------------------
__device__ __forceinline__ unsigned f2tf(float f) {
    unsigned u;
    asm("cvt.rna.tf32.f32 %0, %1;" : "=r"(u) : "f"(f));
    return u;
}
__device__ __forceinline__ float f2tff(float f) { return __uint_as_float(f2tf(f)); }

__device__ __forceinline__ void mma_tf32(float* c, const unsigned* a, const unsigned* b) {
    asm volatile(
        "mma.sync.aligned.m16n8k8.row.col.f32.tf32.tf32.f32 "
        "{%0,%1,%2,%3}, {%4,%5,%6,%7}, {%8,%9}, {%0,%1,%2,%3};"
        : "+f"(c[0]), "+f"(c[1]), "+f"(c[2]), "+f"(c[3])
        : "r"(a[0]), "r"(a[1]), "r"(a[2]), "r"(a[3]), "r"(b[0]), "r"(b[1]));
}

#define CP16(dst, src) \
    asm volatile("cp.async.cg.shared.global [%0], [%1], 16;" :: "r"(dst), "l"(src))
#define CP_COMMIT() asm volatile("cp.async.commit_group;")
#define CP_WAIT1()  asm volatile("cp.async.wait_group 1;")

// ---------------- tf32 GEMM v3: cp.async 3-stage, 512 threads -------------------
// Block tile 256(M) x 128(N) x 32(K). 16 warps as 4(m) x 4(n), warp tile 64x32.
// Operands must already be tf32-rounded fp32 bit patterns.
// Smem layouts (words):
//   TA=0: As[m][k]  stride 36   TA=1: As[k][m]  stride 264
//   TB=1: Bs[n][k]  stride 36   TB=0: Bs[k][n]  stride 136
// MODE: 0 plain, 1 causal tile-skip, 2 causal K-limit. ROUND: tf32-round output.
#define ASZW 9216            // max A stage words (256*36)
#define BSZW 4608            // max B stage words (128*36)
#define STAGEW (ASZW + BSZW) // 13824 words
#define SMEM_BYTES (3 * STAGEW * 4)  // 165888 B

template <bool TA, bool TB, int MODE, bool ROUND>
__global__ void __launch_bounds__(512, 1) gemm_tc3(
        const float* __restrict__ A, const float* __restrict__ B,
        float* __restrict__ C, int M, int N, int K,
        int lda, int ldb, int ldc,
        long long sAq, long long sAr, long long sBq, long long sBr,
        long long sCq, long long sCr, int zdiv) {
    const int m0 = blockIdx.y * 256;
    const int n0 = blockIdx.x * 128;
    if (MODE == 1 && n0 >= m0 + 256) return;

    int z = blockIdx.z;
    int zq = z / zdiv, zr = z % zdiv;
    A += (long long)zq * sAq + (long long)zr * sAr;
    B += (long long)zq * sBq + (long long)zr * sBr;
    C += (long long)zq * sCq + (long long)zr * sCr;

    const int Keff = (MODE == 2) ? ((m0 + 256 < K) ? m0 + 256 : K) : K;
    const int ntiles = Keff >> 5;

    extern __shared__ float sh[];
    const unsigned shb = (unsigned)__cvta_generic_to_shared(sh);

    const int tid  = threadIdx.x;
    const int lane = tid & 31;
    const int warp = tid >> 5;
    const int wm = (warp >> 2) * 64;   // 0,64,128,192
    const int wn = (warp & 3) * 32;    // 0,32,64,96
    const int lane4 = lane & 3;
    const int laneg = lane >> 2;

    float acc[4][4][4] = {};

    auto issue = [&](int t) {
        const int k0 = t << 5;
        const unsigned As = shb + (t % 3) * (STAGEW * 4);
        const unsigned Bs = As + ASZW * 4;
        if (!TA) {
            const int row = tid >> 1;
            const float* src = A + (long long)(m0 + row) * lda + k0 + (tid & 1) * 16;
            const unsigned dst = As + (row * 36 + (tid & 1) * 16) * 4;
#pragma unroll
            for (int i = 0; i < 4; i++) CP16(dst + i * 16, src + i * 4);
        } else {
            const int k = tid >> 4, f4 = (tid & 15) * 4;
            const float* src = A + (long long)(k0 + k) * lda + m0 + f4 * 4;
            const unsigned dst = As + (k * 264 + f4 * 4) * 4;
#pragma unroll
            for (int i = 0; i < 4; i++) CP16(dst + i * 16, src + i * 4);
        }
        if (TB) {
            const int n = tid >> 2, f4 = (tid & 3) * 2;
            const float* src = B + (long long)(n0 + n) * ldb + k0 + f4 * 4;
            const unsigned dst = Bs + (n * 36 + f4 * 4) * 4;
#pragma unroll
            for (int i = 0; i < 2; i++) CP16(dst + i * 16, src + i * 4);
        } else {
            const int k = tid >> 4, f4 = (tid & 15) * 2;
            const float* src = B + (long long)(k0 + k) * ldb + n0 + f4 * 4;
            const unsigned dst = Bs + (k * 136 + f4 * 4) * 4;
#pragma unroll
            for (int i = 0; i < 2; i++) CP16(dst + i * 16, src + i * 4);
        }
        CP_COMMIT();
    };

    issue(0);
    if (ntiles > 1) issue(1);

    for (int t = 0; t < ntiles; t++) {
        CP_WAIT1();
        __syncthreads();
        if (t + 2 < ntiles) issue(t + 2);

        const unsigned* As = (const unsigned*)sh + (t % 3) * STAGEW;
        const unsigned* Bs = As + ASZW;

#pragma unroll
        for (int kk = 0; kk < 32; kk += 8) {
            const int k1 = kk + lane4, k2 = k1 + 4;
            unsigned a[4][4], b[4][2];
#pragma unroll
            for (int mi = 0; mi < 4; mi++) {
                const int mr = wm + mi * 16 + laneg;
                if (!TA) {
                    a[mi][0] = As[mr * 36 + k1];
                    a[mi][1] = As[(mr + 8) * 36 + k1];
                    a[mi][2] = As[mr * 36 + k2];
                    a[mi][3] = As[(mr + 8) * 36 + k2];
                } else {
                    a[mi][0] = As[k1 * 264 + mr];
                    a[mi][1] = As[k1 * 264 + mr + 8];
                    a[mi][2] = As[k2 * 264 + mr];
                    a[mi][3] = As[k2 * 264 + mr + 8];
                }
            }
#pragma unroll
            for (int ni = 0; ni < 4; ni++) {
                const int nc = wn + ni * 8 + laneg;
                if (TB) {
                    b[ni][0] = Bs[nc * 36 + k1];
                    b[ni][1] = Bs[nc * 36 + k2];
                } else {
                    b[ni][0] = Bs[k1 * 136 + nc];
                    b[ni][1] = Bs[k2 * 136 + nc];
                }
            }
#pragma unroll
            for (int mi = 0; mi < 4; mi++)
#pragma unroll
                for (int ni = 0; ni < 4; ni++)
                    mma_tf32(acc[mi][ni], a[mi], b[ni]);
        }
        __syncthreads();
    }

#pragma unroll
    for (int mi = 0; mi < 4; mi++) {
#pragma unroll
        for (int ni = 0; ni < 4; ni++) {
            const int row = m0 + wm + mi * 16 + laneg;
            const int col = n0 + wn + ni * 8 + lane4 * 2;
            float v0 = acc[mi][ni][0], v1 = acc[mi][ni][1];
            float v2 = acc[mi][ni][2], v3 = acc[mi][ni][3];
            if (ROUND) { v0 = f2tff(v0); v1 = f2tff(v1); v2 = f2tff(v2); v3 = f2tff(v3); }
            *reinterpret_cast<float2*>(&C[(long long)row * ldc + col]) = make_float2(v0, v1);
            *reinterpret_cast<float2*>(&C[(long long)(row + 8) * ldc + col]) = make_float2(v2, v3);
        }
    }
}

// ---------------- tf32 round-copy ----------------------------------------------
__global__ void round_copy(const float* __restrict__ in, float* __restrict__ out, int n4) {
    int idx = blockIdx.x * blockDim.x + threadIdx.x;
    if (idx >= n4) return;
    float4 v = reinterpret_cast<const float4*>(in)[idx];
    v.x = f2tff(v.x); v.y = f2tff(v.y); v.z = f2tff(v.z); v.w = f2tff(v.w);
    reinterpret_cast<float4*>(out)[idx] = v;
}

// ---------------- weight concat: Wcat = [W_dq ; W_kr ; pad] (rounded) -----------
__global__ void build_wcat(const float* __restrict__ Wdq,
                           const float* __restrict__ Wkr,
                           float* __restrict__ Wcat) {
    int idx = blockIdx.x * blockDim.x + threadIdx.x;
    if (idx >= 576 * 512) return;
    int row = idx >> 9, c4 = idx & 511;
    float4 v = (row < 512)
        ? reinterpret_cast<const float4*>(Wdq)[row * 512 + c4]
        : reinterpret_cast<const float4*>(Wkr)[(row - 512) * 512 + c4];
    v.x = f2tff(v.x); v.y = f2tff(v.y); v.z = f2tff(v.z); v.w = f2tff(v.w);
    reinterpret_cast<float4*>(Wcat)[row * 512 + c4] = v;
}

// ---------------- rope (tf32-rounded outputs) -----------------------------------
__global__ void rope_q_kernel(const float* __restrict__ cqr,
                              const float* __restrict__ fc,
                              const float* __restrict__ fs,
                              float* __restrict__ qcat) {
    int idx = blockIdx.x * blockDim.x + threadIdx.x;
    if (idx >= 4 * 1024 * 16 * 32) return;
    int j = idx & 31;
    int h = (idx >> 5) & 15;
    int t = (idx >> 9) & 1023;
    int b = idx >> 19;
    long long src = (((long long)(b * 1024 + t)) * 1024) + h * 64 + 2 * j;
    float re = cqr[src], im = cqr[src + 1];
    float c = fc[t * 32 + j], s = fs[t * 32 + j];
    long long dst = (((long long)(b * 16 + h)) * 1024 + t) * 576 + 512 + 2 * j;
    qcat[dst]     = f2tff(re * c - im * s);
    qcat[dst + 1] = f2tff(re * s + im * c);
}

__global__ void rope_k_kernel(const float* __restrict__ cqx,
                              const float* __restrict__ fc,
                              const float* __restrict__ fs,
                              float* __restrict__ kcat) {
    int idx = blockIdx.x * blockDim.x + threadIdx.x;
    if (idx >= 4 * 1024 * 32) return;
    int j = idx & 31;
    int t = (idx >> 5) & 1023;
    int b = idx >> 15;
    long long src = ((long long)(b * 1024 + t)) * 640 + 512 + 2 * j;
    float re = cqx[src], im = cqx[src + 1];
    float c = fc[t * 32 + j], s = fs[t * 32 + j];
    long long dst = ((long long)(b * 1024 + t)) * 576 + 512 + 2 * j;
    kcat[dst]     = f2tff(re * c - im * s);
    kcat[dst + 1] = f2tff(re * s + im * c);
}

// ---------------- softmax (in place, tf32-rounded P) ----------------------------
__global__ void softmax_kernel(float* __restrict__ L) {
    const int r = blockIdx.x;
    const int t = r & 1023;
    float* row = L + (long long)r * 1024;
    const float scale = 0.07216878364870323f;
    const int tid = threadIdx.x;  // 128
    __shared__ float red[128];

    float m = -INFINITY;
    for (int s = tid; s <= t; s += 128) m = fmaxf(m, row[s]);
    red[tid] = m;
    __syncthreads();
    for (int o = 64; o; o >>= 1) {
        if (tid < o) red[tid] = fmaxf(red[tid], red[tid + o]);
        __syncthreads();
    }
    m = red[0] * scale;
    __syncthreads();

    float sum = 0.0f;
    for (int s = tid; s <= t; s += 128) sum += __expf(row[s] * scale - m);
    red[tid] = sum;
    __syncthreads();
    for (int o = 64; o; o >>= 1) {
        if (tid < o) red[tid] += red[tid + o];
        __syncthreads();
    }
    float inv = 1.0f / red[0];
    __syncthreads();

    for (int s = tid; s < 1024; s += 128)
        row[s] = (s <= t) ? f2tff(__expf(row[s] * scale - m) * inv) : 0.0f;
}

// ---------------- launcher -------------------------------------------------------
extern "C" void kernel_launch(void* const* d_in, const int* in_sizes, int n_in,
                              void* d_out, int out_size) {
    (void)in_sizes; (void)n_in; (void)out_size;
    const float* x     = (const float*)d_in[0];
    const float* W_dq  = (const float*)d_in[1];
    const float* W_uq  = (const float*)d_in[2];
    const float* W_dkv = (const float*)d_in[3];
    const float* W_uk  = (const float*)d_in[4];
    const float* W_uv  = (const float*)d_in[5];
    const float* W_o   = (const float*)d_in[6];
    const float* W_qr  = (const float*)d_in[7];
    const float* W_kr  = (const float*)d_in[8];
    const float* fc    = (const float*)d_in[9];
    const float* fs    = (const float*)d_in[10];
    float* out = (float*)d_out;

    float *keff, *Mm, *wcat, *xr, *wdkv, *wqr, *wuq, *wuk, *wuv, *wo;
    float *cqx, *cqr, *qcat, *kcat, *logits;
    cudaGetSymbolAddress((void**)&keff,   g_keff);
    cudaGetSymbolAddress((void**)&Mm,     g_M);
    cudaGetSymbolAddress((void**)&wcat,   g_wcat);
    cudaGetSymbolAddress((void**)&xr,     g_xr);
    cudaGetSymbolAddress((void**)&wdkv,   g_wdkv);
    cudaGetSymbolAddress((void**)&wqr,    g_wqr);
    cudaGetSymbolAddress((void**)&wuq,    g_wuq);
    cudaGetSymbolAddress((void**)&wuk,    g_wuk);
    cudaGetSymbolAddress((void**)&wuv,    g_wuv);
    cudaGetSymbolAddress((void**)&wo,     g_wo);
    cudaGetSymbolAddress((void**)&cqx,    g_cqx);
    cudaGetSymbolAddress((void**)&cqr,    g_cqr);
    cudaGetSymbolAddress((void**)&qcat,   g_qcat);
    cudaGetSymbolAddress((void**)&kcat,   g_kcat);
    cudaGetSymbolAddress((void**)&logits, g_logits);

    cudaFuncSetAttribute(gemm_tc3<false, true,  0, true >, cudaFuncAttributeMaxDynamicSharedMemorySize, SMEM_BYTES);
    cudaFuncSetAttribute(gemm_tc3<false, false, 0, true >, cudaFuncAttributeMaxDynamicSharedMemorySize, SMEM_BYTES);
    cudaFuncSetAttribute(gemm_tc3<true,  true,  0, true >, cudaFuncAttributeMaxDynamicSharedMemorySize, SMEM_BYTES);
    cudaFuncSetAttribute(gemm_tc3<false, true,  0, false>, cudaFuncAttributeMaxDynamicSharedMemorySize, SMEM_BYTES);
    cudaFuncSetAttribute(gemm_tc3<false, true,  1, false>, cudaFuncAttributeMaxDynamicSharedMemorySize, SMEM_BYTES);
    cudaFuncSetAttribute(gemm_tc3<false, false, 2, true >, cudaFuncAttributeMaxDynamicSharedMemorySize, SMEM_BYTES);
    cudaFuncSetAttribute(gemm_tc3<false, false, 0, false>, cudaFuncAttributeMaxDynamicSharedMemorySize, SMEM_BYTES);

    dim3 blk(512);
    const long long QZ = 1024LL * 576;
    const long long KZ = 1024LL * 576;
    const long long LZ = 1024LL * 1024;
    const long long YZ = 1024LL * 512;

    // --- pre-round operands to tf32 ---
    round_copy<<<(2097152 + 255) / 256, 256>>>(x,     xr,   2097152);  // 8.4M floats
    round_copy<<<(262144  + 255) / 256, 256>>>(W_dkv, wdkv, 262144);
    round_copy<<<(131072  + 255) / 256, 256>>>(W_qr,  wqr,  131072);
    round_copy<<<(262144  + 255) / 256, 256>>>(W_uq,  wuq,  262144);
    round_copy<<<(262144  + 255) / 256, 256>>>(W_uk,  wuk,  262144);
    round_copy<<<(262144  + 255) / 256, 256>>>(W_uv,  wuv,  262144);
    round_copy<<<(1048576 + 255) / 256, 256>>>(W_o,   wo,   1048576);
    build_wcat<<<(576 * 512 + 255) / 256, 256>>>(W_dq, W_kr, wcat);

    // 1) cqx (4096x640) = x @ Wcat^T
    gemm_tc3<false, true, 0, true><<<dim3(5, 16, 1), blk, SMEM_BYTES>>>(
        xr, wcat, cqx, 4096, 640, 2048, 2048, 2048, 640,
        0, 0, 0, 0, 0, 0, 1);

    // 2) kcat[:, 0:512] = x @ W_dkv^T
    gemm_tc3<false, true, 0, true><<<dim3(4, 16, 1), blk, SMEM_BYTES>>>(
        xr, wdkv, kcat, 4096, 512, 2048, 2048, 2048, 576,
        0, 0, 0, 0, 0, 0, 1);

    // 3) k_eff[h] = Wuq_slice @ Wuk_slice
    gemm_tc3<false, false, 0, true><<<dim3(4, 2, 16), blk, SMEM_BYTES>>>(
        wuq, wuk, keff, 512, 512, 128, 2048, 512, 512,
        128, 0, 128LL * 512, 0, 512LL * 512, 0, 1);

    // 4) M = W_uv^T @ W_o^T
    gemm_tc3<true, true, 0, true><<<dim3(16, 2, 1), blk, SMEM_BYTES>>>(
        wuv, wo, Mm, 512, 2048, 2048, 512, 2048, 2048,
        0, 0, 0, 0, 0, 0, 1);

    // 5) c_qr = c_q @ W_qr^T   (no round; rope rounds)
    gemm_tc3<false, true, 0, false><<<dim3(8, 16, 1), blk, SMEM_BYTES>>>(
        cqx, wqr, cqr, 4096, 1024, 512, 640, 512, 1024,
        0, 0, 0, 0, 0, 0, 1);

    // 6) rope into concat tails
    rope_q_kernel<<<8192, 256>>>(cqr, fc, fs, qcat);
    rope_k_kernel<<<512, 256>>>(cqx, fc, fs, kcat);

    // 7) q_abs -> qcat[:, 0:512] = c_q[b] @ k_eff[h]
    gemm_tc3<false, false, 0, true><<<dim3(4, 4, 64), blk, SMEM_BYTES>>>(
        cqx, keff, qcat, 1024, 512, 512, 640, 512, 576,
        1024LL * 640, 0, 0, 512LL * 512,
        16LL * QZ, QZ, 16);

    // 8) logits = qcat @ kcat^T (K=576), causal tile-skip
    gemm_tc3<false, true, 1, false><<<dim3(8, 4, 64), blk, SMEM_BYTES>>>(
        qcat, kcat, logits, 1024, 1024, 576, 576, 576, 1024,
        16LL * QZ, QZ, KZ, 0,
        16LL * LZ, LZ, 16);

    // 9) softmax
    softmax_kernel<<<65536, 128>>>(logits);

    // 10) y_c = P @ c_kv, causal K-limit
    gemm_tc3<false, false, 2, true><<<dim3(4, 4, 64), blk, SMEM_BYTES>>>(
        logits, kcat, qcat, 1024, 512, 1024, 1024, 576, 512,
        16LL * LZ, LZ, KZ, 0,
        16LL * YZ, YZ, 16);

    // 11) out = y_c @ M slices
    gemm_tc3<false, false, 0, false><<<dim3(1, 4, 64), blk, SMEM_BYTES>>>(
        qcat, Mm, out, 1024, 128, 512, 512, 2048, 2048,
        16LL * YZ, YZ, 0, 128,
        1024LL * 2048, 128, 16);
}